// round 6
// baseline (speedup 1.0000x reference)
#include <cuda_runtime.h>
#include <math.h>

typedef unsigned long long ull;

#define Nn 4096
#define Hd 64
#define Gg 32
#define NTOPK 6
#define TWO_PI_F 6.2831853071795864769f

#define MAXC16 320
#define MAXC32 192

// ---------------- scratch ----------------
__device__ float g_q[Nn * Hd];                 // silu(q) * 0.125
__device__ float g_k[Nn * Hd];                 // silu(k)
__device__ float g_v[Nn * Hd];
__device__ float g_KV[Gg * NTOPK * Hd * Hd];   // per (graph, m) 64x64
__device__ float g_kvec[Gg * NTOPK * 3];
__device__ int   g_start[Gg + 1];
__device__ int   g_list16[MAXC16];
__device__ int   g_list32[MAXC32];
__device__ int   g_n16;
__device__ int   g_n32;

// ---------------- f32x2 helpers ----------------
__device__ __forceinline__ ull dup2(float x) {
    ull r; asm("mov.b64 %0, {%1, %1};" : "=l"(r) : "f"(x)); return r;
}
__device__ __forceinline__ void unpack2(ull a, float& x, float& y) {
    asm("mov.b64 {%0, %1}, %2;" : "=f"(x), "=f"(y) : "l"(a));
}
__device__ __forceinline__ void fma2(ull& d, ull a, ull b) {
    asm("fma.rn.f32x2 %0, %1, %2, %0;" : "+l"(d) : "l"(a), "l"(b));
}
__device__ __forceinline__ void red2(float* p, float a, float b) {
    asm volatile("red.global.add.v2.f32 [%0], {%1, %2};" :: "l"(p), "f"(a), "f"(b) : "memory");
}

// =====================================================================
// Kernel 1: k-grid top-6 per graph + offsets + chunk lists.
// =====================================================================
__global__ __launch_bounds__(1024) void k_setup(const float* __restrict__ cell,
                                                const int* __restrict__ batch) {
    int t = threadIdx.x;
    int w = t >> 5, lane = t & 31;

    if (t <= Gg) {
        int lo = 0, hi = Nn;
        while (lo < hi) {
            int mid = (lo + hi) >> 1;
            if (batch[mid] < t) lo = mid + 1; else hi = mid;
        }
        g_start[t] = lo;
    }

    if (w < Gg) {
        float ix = 1.0f / cell[w * 9 + 0];
        float iy = 1.0f / cell[w * 9 + 4];
        float iz = 1.0f / cell[w * 9 + 8];
        const float k2max = (TWO_PI_F / 10.0f) * (TWO_PI_F / 10.0f);

        ull keys[11];
        int nk = 0;
        for (int idx = lane; idx < 342; idx += 32) {
            int L = idx + (idx >= 171 ? 1 : 0);
            int a = L / 49 - 3;
            int b = (L / 7) % 7 - 3;
            int c = L % 7 - 3;
            float kx = (TWO_PI_F * (float)a) * ix;
            float ky = (TWO_PI_F * (float)b) * iy;
            float kz = (TWO_PI_F * (float)c) * iz;
            float ksq = kx * kx + ky * ky + kz * kz;
            float eff = (ksq <= k2max) ? ksq : 1e10f;
            keys[nk++] = (((ull)__float_as_uint(eff)) << 32) | (unsigned)idx;
        }

        ull prev = 0;
        for (int s = 0; s < NTOPK; s++) {
            ull best = ~0ULL;
            #pragma unroll
            for (int i = 0; i < 11; i++)
                if (i < nk) {
                    ull kk = keys[i];
                    if (kk > prev && kk < best) best = kk;
                }
            for (int off = 16; off; off >>= 1) {
                ull o = __shfl_xor_sync(0xffffffffu, best, off);
                if (o < best) best = o;
            }
            best = __shfl_sync(0xffffffffu, best, 0);
            prev = best;
            if (lane == 0) {
                int bi = (int)(best & 0xffffffffULL);
                int L = bi + (bi >= 171 ? 1 : 0);
                int a = L / 49 - 3;
                int b = (L / 7) % 7 - 3;
                int c = L % 7 - 3;
                g_kvec[(w * NTOPK + s) * 3 + 0] = (TWO_PI_F * (float)a) * ix;
                g_kvec[(w * NTOPK + s) * 3 + 1] = (TWO_PI_F * (float)b) * iy;
                g_kvec[(w * NTOPK + s) * 3 + 2] = (TWO_PI_F * (float)c) * iz;
            }
        }
    }

    __syncthreads();
    if (t == 0) {
        int i16 = 0, i32 = 0;
        for (int g = 0; g < Gg; g++) {
            int n0 = g_start[g], n1 = g_start[g + 1];
            for (int s = n0; s < n1; s += 16)
                g_list16[i16++] = s | (g << 13) | (min(16, n1 - s) << 18);
            for (int s = n0; s < n1; s += 32)
                g_list32[i32++] = s | (g << 13) | (min(32, n1 - s) << 18);
        }
        g_n16 = i16;
        g_n32 = i32;
    }
}

// =====================================================================
// Kernel 2: QKV projection + silu.
// =====================================================================
__global__ __launch_bounds__(256) void k_qkv(const float* __restrict__ x,
                                             const float* __restrict__ W) {
    __shared__ float wt[64 * 98];
    __shared__ float xs[64 * 34];

    int bx = blockIdx.x;
    int nb = bx >> 1;
    int jh = bx & 1;
    int t = threadIdx.x;

    for (int s = t; s < 96 * 16; s += 256) {
        int j = s >> 4, h0 = (s & 15) * 4;
        float4 wv = *(const float4*)&W[(jh * 96 + j) * 64 + h0];
        wt[(h0 + 0) * 98 + j] = wv.x;
        wt[(h0 + 1) * 98 + j] = wv.y;
        wt[(h0 + 2) * 98 + j] = wv.z;
        wt[(h0 + 3) * 98 + j] = wv.w;
    }
    for (int s = t; s < 512; s += 256) {
        int nl = s >> 4, h0 = (s & 15) * 4;
        float4 xv = *(const float4*)&x[(nb * 32 + nl) * 64 + h0];
        xs[(h0 + 0) * 34 + nl] = xv.x;
        xs[(h0 + 1) * 34 + nl] = xv.y;
        xs[(h0 + 2) * 34 + nl] = xv.z;
        xs[(h0 + 3) * 34 + nl] = xv.w;
    }
    __syncthreads();

    int ng = t & 15;
    int jg = t >> 4;
    int j0 = jg * 6;

    ull acc[3][2];
    #pragma unroll
    for (int i = 0; i < 3; i++) { acc[i][0] = 0ULL; acc[i][1] = 0ULL; }

    #pragma unroll 8
    for (int h = 0; h < 64; h++) {
        float xa = xs[h * 34 + ng * 2];
        float xb = xs[h * 34 + ng * 2 + 1];
        ull xda = dup2(xa), xdb = dup2(xb);
        ull w01 = *(ull*)&wt[h * 98 + j0];
        ull w23 = *(ull*)&wt[h * 98 + j0 + 2];
        ull w45 = *(ull*)&wt[h * 98 + j0 + 4];
        fma2(acc[0][0], w01, xda); fma2(acc[0][1], w01, xdb);
        fma2(acc[1][0], w23, xda); fma2(acc[1][1], w23, xdb);
        fma2(acc[2][0], w45, xda); fma2(acc[2][1], w45, xdb);
    }

    #pragma unroll
    for (int jp = 0; jp < 3; jp++) {
        #pragma unroll
        for (int nn = 0; nn < 2; nn++) {
            float v0, v1;
            unpack2(acc[jp][nn], v0, v1);
            int n = nb * 32 + ng * 2 + nn;
            #pragma unroll
            for (int ii = 0; ii < 2; ii++) {
                float val = ii ? v1 : v0;
                int j = jh * 96 + j0 + jp * 2 + ii;
                if (j < 128) val = val / (1.0f + expf(-val));
                if (j < 64)        g_q[n * 64 + j] = val * 0.125f;
                else if (j < 128)  g_k[n * 64 + (j - 64)] = val;
                else               g_v[n * 64 + (j - 128)] = val;
            }
        }
    }
}

// =====================================================================
// Kernel 3: KV accumulation. CTA = (chunk32, m); all-smem inner loop.
// =====================================================================
__global__ __launch_bounds__(256) void k_kv(const float* __restrict__ pos) {
    int chunk = blockIdx.x / NTOPK;
    int m = blockIdx.x % NTOPK;
    if (chunk >= g_n32) return;
    int meta = g_list32[chunk];
    int base = meta & 0x1FFF;
    int g = (meta >> 13) & 31;
    int cnt = meta >> 18;

    __shared__ ull   krd[32 * 64];
    __shared__ float vs[32 * 64];
    __shared__ float2 cs_s[32];

    int t = threadIdx.x;
    int eg = t & 15;
    int hg = t >> 4;

    float kvx = g_kvec[(g * NTOPK + m) * 3 + 0];
    float kvy = g_kvec[(g * NTOPK + m) * 3 + 1];
    float kvz = g_kvec[(g * NTOPK + m) * 3 + 2];

    if (t < cnt) {
        int n = base + t;
        float ph = pos[n * 3 + 0] * kvx + pos[n * 3 + 1] * kvy + pos[n * 3 + 2] * kvz;
        float sn, cn;
        sincosf(ph, &sn, &cn);
        cs_s[t] = make_float2(cn, sn);
    }
    for (int s = t; s < cnt * 16; s += 256)
        *(float4*)&vs[s * 4] = *(const float4*)&g_v[base * 64 + s * 4];
    __syncthreads();
    for (int s = t; s < cnt * 64; s += 256) {
        int nn = s >> 6, h = s & 63;
        float2 cc = cs_s[nn];
        float k1 = g_k[(base + nn) * 64 + (h & 31)];
        float k2 = g_k[(base + nn) * 64 + (h & 31) + 32];
        float kr = (h < 32) ? (k1 * cc.x - k2 * cc.y) : (k1 * cc.y + k2 * cc.x);
        krd[s] = dup2(kr);
    }
    __syncthreads();

    ull acc[4][2];
    #pragma unroll
    for (int i = 0; i < 4; i++) { acc[i][0] = 0ULL; acc[i][1] = 0ULL; }

    #pragma unroll 4
    for (int nn = 0; nn < cnt; nn++) {
        ulonglong2 ka = *(const ulonglong2*)&krd[nn * 64 + hg * 4];
        ulonglong2 kb = *(const ulonglong2*)&krd[nn * 64 + hg * 4 + 2];
        ulonglong2 vv = *(const ulonglong2*)&vs[nn * 64 + eg * 4];
        fma2(acc[0][0], ka.x, vv.x); fma2(acc[0][1], ka.x, vv.y);
        fma2(acc[1][0], ka.y, vv.x); fma2(acc[1][1], ka.y, vv.y);
        fma2(acc[2][0], kb.x, vv.x); fma2(acc[2][1], kb.x, vv.y);
        fma2(acc[3][0], kb.y, vv.x); fma2(acc[3][1], kb.y, vv.y);
    }

    float* dst = g_KV + (size_t)(g * NTOPK + m) * 4096;
    #pragma unroll
    for (int hh = 0; hh < 4; hh++) {
        float a0, a1, a2, a3;
        unpack2(acc[hh][0], a0, a1);
        unpack2(acc[hh][1], a2, a3);
        float* p = &dst[(hg * 4 + hh) * 64 + eg * 4];
        red2(p, a0, a1);
        red2(p + 2, a2, a3);
    }
}

// =====================================================================
// Kernel 4: update. Grid = MAXC32*3; CTA = (chunk32, m-pair). 128 threads.
// Thread: np = t>>3 (nodes 2np,2np+1), eq = t&7 (e octet eq*8).
// Inner loop/h: 3 LDS + 8 FFMA2. red.v2 epilogue into zeroed out.
// =====================================================================
__global__ __launch_bounds__(128) void k_upd(const float* __restrict__ pos,
                                             float* __restrict__ out) {
    int b = blockIdx.x;
    int chunk = b / 3, mp = b % 3;
    if (chunk >= g_n32) return;
    int meta = g_list32[chunk];
    int base = meta & 0x1FFF;
    int g = (meta >> 13) & 31;
    int cnt = meta >> 18;

    __shared__ float  qtile_t[64 * 33];   // [h][node], pad 33
    __shared__ float2 cs_s[2 * 32];
    __shared__ ull    qrd[64 * 34];       // [h][node] dup'd, pad 34
    __shared__ float  kvs[64 * 64];       // [h][e]

    int t = threadIdx.x;
    int np = t >> 3;    // 0..15
    int eq = t & 7;     // 0..7

    // stage q transposed: thread -> node = t>>2, h0 = (t&3)*16
    {
        int node = t >> 2, h0 = (t & 3) * 16;
        int n = min(base + node, Nn - 1);
        #pragma unroll
        for (int i = 0; i < 4; i++) {
            float4 qv = *(const float4*)&g_q[n * 64 + h0 + i * 4];
            qtile_t[(h0 + i * 4 + 0) * 33 + node] = qv.x;
            qtile_t[(h0 + i * 4 + 1) * 33 + node] = qv.y;
            qtile_t[(h0 + i * 4 + 2) * 33 + node] = qv.z;
            qtile_t[(h0 + i * 4 + 3) * 33 + node] = qv.w;
        }
    }
    // cos/sin for the 2 m of this CTA
    if (t < 64) {
        int mm = t >> 5, node = t & 31;
        int m = mp * 2 + mm;
        float kvx = g_kvec[(g * NTOPK + m) * 3 + 0];
        float kvy = g_kvec[(g * NTOPK + m) * 3 + 1];
        float kvz = g_kvec[(g * NTOPK + m) * 3 + 2];
        int n = min(base + node, Nn - 1);
        float ph = pos[n * 3 + 0] * kvx + pos[n * 3 + 1] * kvy + pos[n * 3 + 2] * kvz;
        float sn, cn;
        sincosf(ph, &sn, &cn);
        cs_s[t] = make_float2(cn, sn);
    }

    // prefetch KV for first m
    float4 pf[8];
    {
        const float* kv0 = g_KV + (size_t)(g * NTOPK + mp * 2) * 4096;
        #pragma unroll
        for (int i = 0; i < 8; i++) pf[i] = *(const float4*)&kv0[(i * 128 + t) * 4];
    }

    ull accA0 = 0, accA1 = 0, accA2 = 0, accA3 = 0;
    ull accB0 = 0, accB1 = 0, accB2 = 0, accB3 = 0;
    __syncthreads();

    #pragma unroll
    for (int mm = 0; mm < 2; mm++) {
        // commit KV tile
        #pragma unroll
        for (int i = 0; i < 8; i++) *(float4*)&kvs[(i * 128 + t) * 4] = pf[i];
        // rope'd q dup'd: node-major order -> conflict-free STS.64
        #pragma unroll
        for (int i = 0; i < 16; i++) {
            int s = i * 128 + t;
            int node = s & 31, h = s >> 5;
            float2 cc = cs_s[mm * 32 + node];
            float q1 = qtile_t[(h & 31) * 33 + node];
            float q2 = qtile_t[((h & 31) + 32) * 33 + node];
            float qr = (h < 32) ? (q1 * cc.x - q2 * cc.y) : (q1 * cc.y + q2 * cc.x);
            qrd[h * 34 + node] = dup2(qr);
        }
        __syncthreads();

        if (mm == 0) {  // prefetch second m during compute
            const float* kvn = g_KV + (size_t)(g * NTOPK + mp * 2 + 1) * 4096;
            #pragma unroll
            for (int i = 0; i < 8; i++) pf[i] = *(const float4*)&kvn[(i * 128 + t) * 4];
        }

        #pragma unroll 8
        for (int h = 0; h < 64; h++) {
            ulonglong2 qq = *(const ulonglong2*)&qrd[h * 34 + 2 * np];
            ulonglong2 ka = *(const ulonglong2*)&kvs[h * 64 + eq * 8];
            ulonglong2 kb = *(const ulonglong2*)&kvs[h * 64 + eq * 8 + 4];
            fma2(accA0, qq.x, ka.x); fma2(accA1, qq.x, ka.y);
            fma2(accA2, qq.x, kb.x); fma2(accA3, qq.x, kb.y);
            fma2(accB0, qq.y, ka.x); fma2(accB1, qq.y, ka.y);
            fma2(accB2, qq.y, kb.x); fma2(accB3, qq.y, kb.y);
        }
        __syncthreads();
    }

    int na = base + 2 * np;
    if (2 * np < cnt) {
        float x0, x1, x2, x3, x4, x5, x6, x7;
        unpack2(accA0, x0, x1); unpack2(accA1, x2, x3);
        unpack2(accA2, x4, x5); unpack2(accA3, x6, x7);
        float* p = &out[na * 64 + eq * 8];
        red2(p, x0, x1); red2(p + 2, x2, x3);
        red2(p + 4, x4, x5); red2(p + 6, x6, x7);
    }
    if (2 * np + 1 < cnt) {
        float x0, x1, x2, x3, x4, x5, x6, x7;
        unpack2(accB0, x0, x1); unpack2(accB1, x2, x3);
        unpack2(accB2, x4, x5); unpack2(accB3, x6, x7);
        float* p = &out[(na + 1) * 64 + eq * 8];
        red2(p, x0, x1); red2(p + 2, x2, x3);
        red2(p + 4, x4, x5); red2(p + 6, x6, x7);
    }
}

// =====================================================================
extern "C" void kernel_launch(void* const* d_in, const int* in_sizes, int n_in,
                              void* d_out, int out_size) {
    const float* node_feat = (const float*)d_in[0];
    const float* positions = (const float*)d_in[1];
    const float* cell      = (const float*)d_in[2];
    const int*   batch     = (const int*)d_in[3];
    const float* W_qkv     = (const float*)d_in[4];
    float* out = (float*)d_out;

    void* kv_ptr = nullptr;
    cudaGetSymbolAddress(&kv_ptr, g_KV);

    cudaMemsetAsync(kv_ptr, 0, sizeof(float) * Gg * NTOPK * Hd * Hd);
    cudaMemsetAsync(out, 0, (size_t)out_size * sizeof(float));
    k_setup<<<1, 1024>>>(cell, batch);
    k_qkv<<<256, 256>>>(node_feat, W_qkv);
    k_kv<<<MAXC32 * NTOPK, 256>>>(positions);
    k_upd<<<MAXC32 * 3, 128>>>(positions, out);
    (void)out_size; (void)n_in; (void)in_sizes;
}